// round 5
// baseline (speedup 1.0000x reference)
#include <cuda_runtime.h>
#include <cuda_bf16.h>

// Problem constants
#define Bn 128
#define Ln 1024
#define Dd 256
#define Tt 64

typedef unsigned long long u64;

// Scratch (static device globals: allowed; runtime alloc is not)
__device__ float g_eexp[Bn * Ln * Tt];   // exp(emissions), [B, L, T]
__device__ float g_nll[Bn];              // per-sequence NLL

// ---------- packed f32x2 helpers ----------
__device__ __forceinline__ u64 pack2(float x, float y) {
    u64 r;
    asm("mov.b64 %0, {%1, %2};" : "=l"(r) : "f"(x), "f"(y));
    return r;
}
__device__ __forceinline__ void unpack2(u64 v, float& x, float& y) {
    asm("mov.b64 {%0, %1}, %2;" : "=f"(x), "=f"(y) : "l"(v));
}
__device__ __forceinline__ void ffma2(u64& d, u64 a, u64 b) {
    asm("fma.rn.f32x2 %0, %1, %2, %0;" : "+l"(d) : "l"(a), "l"(b));
}

// =====================================================================
// Kernel 1: emissions = embed[x] @ W + b ;  g_eexp = exp(emissions)
//   256 threads/CTA, 32 tokens/CTA, 8 threads per token, 8 labels/thread.
//   W (64KB) and duplicated-pair embed rows (66.5KB) in dynamic smem.
// =====================================================================
#define ETOK 32
#define EPAD 260   // float2 row stride for esh (pad to avoid bank conflicts)
#define EMIT_SMEM (Dd * Tt * 4 + ETOK * EPAD * 8)

__global__ void __launch_bounds__(256, 1)
emit_kernel(const int* __restrict__ x,
            const float* __restrict__ embed,
            const float* __restrict__ W,
            const float* __restrict__ bias)
{
    extern __shared__ float sm[];
    float*  Wsh = sm;                               // [256][64]
    float2* esh = (float2*)(sm + Dd * Tt);          // [32][EPAD] duplicated pairs

    const int tid = threadIdx.x;

    // Stage W: 4096 float4 across 256 threads
    {
        const float4* W4 = (const float4*)W;
        float4* Wsh4 = (float4*)Wsh;
#pragma unroll
        for (int k = 0; k < 16; k++)
            Wsh4[tid + 256 * k] = W4[tid + 256 * k];
    }

    const int token = tid >> 3;       // 0..31
    const int sub   = tid & 7;        // 0..7
    const int gtok  = blockIdx.x * ETOK + token;
    const int row   = x[gtok];

    // Stage this token's embed row as duplicated (e,e) pairs
    {
        const float4* er = (const float4*)(embed + (size_t)row * Dd);
        float2* ed = esh + token * EPAD;
#pragma unroll
        for (int u = 0; u < 8; u++) {
            float4 v = er[sub + 8 * u];
            int d0 = (sub + 8 * u) * 4;
            ed[d0 + 0] = make_float2(v.x, v.x);
            ed[d0 + 1] = make_float2(v.y, v.y);
            ed[d0 + 2] = make_float2(v.z, v.z);
            ed[d0 + 3] = make_float2(v.w, v.w);
        }
    }
    __syncthreads();

    const int jq = sub * 8;
    const u64* e2 = (const u64*)(esh + token * EPAD);

    u64 a0 = 0ull, a1 = 0ull, a2 = 0ull, a3 = 0ull;   // (0.f,0.f) bit pattern
#pragma unroll 16
    for (int d = 0; d < Dd; d++) {
        u64 ee = e2[d];
        const u64* w2 = (const u64*)(Wsh + d * Tt + jq);
        ffma2(a0, ee, w2[0]);
        ffma2(a1, ee, w2[1]);
        ffma2(a2, ee, w2[2]);
        ffma2(a3, ee, w2[3]);
    }

    float o[8];
    unpack2(a0, o[0], o[1]);
    unpack2(a1, o[2], o[3]);
    unpack2(a2, o[4], o[5]);
    unpack2(a3, o[6], o[7]);

    const float4* b4 = (const float4*)(bias + jq);
    float4 bA = b4[0], bB = b4[1];
    o[0] = __expf(o[0] + bA.x); o[1] = __expf(o[1] + bA.y);
    o[2] = __expf(o[2] + bA.z); o[3] = __expf(o[3] + bA.w);
    o[4] = __expf(o[4] + bB.x); o[5] = __expf(o[5] + bB.y);
    o[6] = __expf(o[6] + bB.z); o[7] = __expf(o[7] + bB.w);

    float4* out4 = (float4*)(g_eexp + (size_t)gtok * Tt + jq);
    out4[0] = make_float4(o[0], o[1], o[2], o[3]);
    out4[1] = make_float4(o[4], o[5], o[6], o[7]);
}

// =====================================================================
// Kernel 2: CRF forward (linear-space with periodic renorm) + gold score
//   1 CTA per sequence, 64 threads (thread j owns state j).
//   E columns cached as packed (E[2i][j], E[2i+1][j]) register pairs.
// =====================================================================
__global__ void __launch_bounds__(64, 1)
crf_kernel(const int* __restrict__ tags, const float* __restrict__ trans)
{
    __shared__ __align__(16) float qs[2][Tt];
    __shared__ float sc[Tt];

    const int b = blockIdx.x;
    const int j = threadIdx.x;

    // exp(trans) column j, packed over i-pairs
    u64 E2[32];
#pragma unroll
    for (int i = 0; i < 32; i++) {
        float ea = __expf(trans[(2 * i) * Tt + j]);
        float eb = __expf(trans[(2 * i + 1) * Tt + j]);
        E2[i] = pack2(ea, eb);
    }
    const float Eend = __expf(trans[j * Tt + 1]);   // exp(trans[j, END])

    const float* ee = g_eexp + (size_t)b * Ln * Tt;
    const int*   tg = tags + b * Ln;

    // ---- gold path score (partial per thread) ----
    float s = 0.f;
    for (int t = j; t < Ln; t += Tt) {
        int tt = tg[t];
        s += __logf(ee[t * Tt + tt]);                       // emission at gold tag
        s += (t == 0) ? trans[tt]                           // trans[START, tag0]
                      : trans[tg[t - 1] * Tt + tt];
        if (t == Ln - 1) s += trans[tt * Tt + 1];           // trans[last, END]
    }
    sc[j] = s;

    // ---- init: q0 = exp(trans[START,j]) * eexp[0,j] ----
    float q = __expf(trans[j]) * ee[j];
    qs[0][j] = q;
    float C = 0.f;
    float eeA = ee[Tt + j];          // t=1 emission (prefetched)
    float eeB = ee[2 * Tt + j];      // t=2
    __syncthreads();

    for (int t = 1; t < Ln; t++) {
        const int rb = (t - 1) & 1;
        float em = eeA;
        eeA = eeB;
        if (t + 2 < Ln) eeB = ee[(t + 2) * Tt + j];

        float rinv = 1.0f;
        const bool rn = ((t & 7) == 0);
        if (rn) {
            const float4* q4 = (const float4*)qs[rb];
            float4 m4 = q4[0];
#pragma unroll
            for (int k = 1; k < 16; k++) {
                float4 v = q4[k];
                m4.x = fmaxf(m4.x, v.x); m4.y = fmaxf(m4.y, v.y);
                m4.z = fmaxf(m4.z, v.z); m4.w = fmaxf(m4.w, v.w);
            }
            float m = fmaxf(fmaxf(m4.x, m4.y), fmaxf(m4.z, m4.w));
            C += __logf(m);
            rinv = __fdividef(1.0f, m);
        }

        const u64* q2 = (const u64*)qs[rb];
        u64 a0 = 0ull, a1 = 0ull, a2 = 0ull, a3 = 0ull;
#pragma unroll
        for (int i = 0; i < 32; i += 4) {
            ffma2(a0, q2[i + 0], E2[i + 0]);
            ffma2(a1, q2[i + 1], E2[i + 1]);
            ffma2(a2, q2[i + 2], E2[i + 2]);
            ffma2(a3, q2[i + 3], E2[i + 3]);
        }
        float f0, f1, f2, f3, f4, f5, f6, f7;
        unpack2(a0, f0, f1); unpack2(a1, f2, f3);
        unpack2(a2, f4, f5); unpack2(a3, f6, f7);
        float dot = ((f0 + f1) + (f2 + f3)) + ((f4 + f5) + (f6 + f7));

        q = dot * em;
        if (rn) q *= rinv;
        qs[t & 1][j] = q;
        __syncthreads();
    }

    // ---- finalize: log Z = C + log(sum_j q_j * exp(trans[j,END])) ----
    qs[0][j] = q * Eend;
    __syncthreads();
    if (j == 0) {
        float Z = 0.f, S = 0.f;
#pragma unroll
        for (int i = 0; i < Tt; i++) { Z += qs[0][i]; S += sc[i]; }
        g_nll[b] = (C + __logf(Z)) - S;
    }
}

// =====================================================================
// Kernel 3: deterministic fixed-order reduce to scalar
// =====================================================================
__global__ void reduce_kernel(float* out)
{
    __shared__ float sh[Bn];
    int i = threadIdx.x;
    sh[i] = g_nll[i];
    __syncthreads();
    if (i == 0) {
        float s = 0.f;
#pragma unroll
        for (int k = 0; k < Bn; k++) s += sh[k];
        out[0] = s;
    }
}

// =====================================================================
// Launch
//   inputs: 0:x(i32) 1:tags(i32) 2:mask(f32, unused) 3:embed 4:W 5:b 6:trans
// =====================================================================
extern "C" void kernel_launch(void* const* d_in, const int* in_sizes, int n_in,
                              void* d_out, int out_size)
{
    const int*   x     = (const int*)d_in[0];
    const int*   tags  = (const int*)d_in[1];
    const float* embed = (const float*)d_in[3];
    const float* W     = (const float*)d_in[4];
    const float* bias  = (const float*)d_in[5];
    const float* trans = (const float*)d_in[6];
    (void)in_sizes; (void)n_in; (void)out_size;

    cudaFuncSetAttribute(emit_kernel,
                         cudaFuncAttributeMaxDynamicSharedMemorySize, EMIT_SMEM);

    emit_kernel<<<(Bn * Ln) / ETOK, 256, EMIT_SMEM>>>(x, embed, W, bias);
    crf_kernel<<<Bn, Tt>>>(tags, trans);
    reduce_kernel<<<1, Bn>>>((float*)d_out);
}

// round 8
// speedup vs baseline: 2.0222x; 2.0222x over previous
#include <cuda_runtime.h>
#include <cuda_bf16.h>
#include <cstdint>

// Problem constants
#define Bn 128
#define Ln 1024
#define Dd 256
#define Tt 64

typedef unsigned long long u64;

// Scratch (static device globals only; runtime alloc forbidden)
__device__ float g_eexp[Bn * Ln * Tt];        // exp(emissions), [B*L, T]
__device__ float g_nll[Bn];                   // per-sequence NLL
__device__ unsigned char g_Wt[Tt * Dd * 2];   // W^T bf16, row-major [64][256] (32KB)

// ---------------- helpers ----------------
__device__ __forceinline__ uint32_t smem_u32(const void* p) {
    uint32_t a;
    asm("{ .reg .u64 t; cvta.to.shared.u64 t, %1; cvt.u32.u64 %0, t; }"
        : "=r"(a) : "l"(p));
    return a;
}
__device__ __forceinline__ u64 pack2(float x, float y) {
    u64 r; asm("mov.b64 %0, {%1, %2};" : "=l"(r) : "f"(x), "f"(y)); return r;
}
__device__ __forceinline__ void unpack2(u64 v, float& x, float& y) {
    asm("mov.b64 {%0, %1}, %2;" : "=f"(x), "=f"(y) : "l"(v));
}
__device__ __forceinline__ void ffma2(u64& d, u64 a, u64 b) {
    asm("fma.rn.f32x2 %0, %1, %2, %0;" : "+l"(d) : "l"(a), "l"(b));
}
__device__ __forceinline__ void lds_v2u64(u64& a, u64& b, uint32_t addr) {
    asm volatile("ld.shared.v2.b64 {%0, %1}, [%2];" : "=l"(a), "=l"(b) : "r"(addr));
}
__device__ __forceinline__ void mma_bf16(float& d0, float& d1, float& d2, float& d3,
                                         uint32_t a0, uint32_t a1, uint32_t a2, uint32_t a3,
                                         uint32_t b0, uint32_t b1) {
    asm volatile(
        "mma.sync.aligned.m16n8k16.row.col.f32.bf16.bf16.f32 "
        "{%0,%1,%2,%3}, {%4,%5,%6,%7}, {%8,%9}, {%0,%1,%2,%3};"
        : "+f"(d0), "+f"(d1), "+f"(d2), "+f"(d3)
        : "r"(a0), "r"(a1), "r"(a2), "r"(a3), "r"(b0), "r"(b1));
}

// =====================================================================
// Kernel 0: one-time W [256][64] fp32 -> g_Wt = W^T bf16 [64][256]
// =====================================================================
__global__ void wt_prep(const float* __restrict__ W)
{
    int tid = threadIdx.x;
    for (int e = tid; e < Tt * Dd / 2; e += 256) {
        int n  = e >> 7;          // 0..63
        int k2 = (e & 127) * 2;   // even k
        __nv_bfloat162 p = __floats2bfloat162_rn(W[k2 * Tt + n], W[(k2 + 1) * Tt + n]);
        *(uint32_t*)(g_Wt + (size_t)n * 512 + k2 * 2) = *(uint32_t*)&p;
    }
}

// =====================================================================
// Kernel 1: emissions via mma.sync bf16; g_eexp = exp(embed[x] @ W + b)
//   CTA: 256 thr = 8 warps; 128 tokens x 64 labels x K=256.
//   Warp w owns token rows [16w, 16w+16), all 64 labels.
//   smem: bias(256B) | A bf16 [128][264] | Bt bf16 [64][264]; stride 528B
//   (row stride 132 words => fragment lane word addr = 4g+tg mod 32, all
//    distinct => conflict-free).
// =====================================================================
#define ASTRIDE 528
#define SM_BIAS 0
#define SM_A    256
#define SM_B    (256 + 128 * ASTRIDE)                 // 67840
#define EMIT_SMEM (SM_B + 64 * ASTRIDE)               // 101632

__global__ void __launch_bounds__(256, 2)
emit_mma(const int* __restrict__ x,
         const float* __restrict__ embed,
         const float* __restrict__ bias)
{
    extern __shared__ char smem[];
    const int tid = threadIdx.x;
    const int wid = tid >> 5, lane = tid & 31;
    const int g = lane >> 2, tg = lane & 3;

    if (tid < Tt) *(float*)(smem + SM_BIAS + tid * 4) = bias[tid];

    // Stage Bt: copy g_Wt row-major with pad. 4 threads/row, 128B each.
    {
        const int row = tid >> 2, seg = tid & 3;
        const uint4* src = (const uint4*)(g_Wt + (size_t)row * 512 + seg * 128);
        uint4* dst = (uint4*)(smem + SM_B + row * ASTRIDE + seg * 128);
#pragma unroll
        for (int i = 0; i < 8; i++) dst[i] = src[i];
    }

    // Stage A: gather embed rows, fp32->bf16. 2 threads/row (k halves).
    {
        const int row = tid >> 1, half = tid & 1;
        const int gtok = blockIdx.x * 128 + row;
        const float4* erow = (const float4*)(embed + (size_t)x[gtok] * Dd) + half * 32;
        char* dst = smem + SM_A + row * ASTRIDE + half * 256;
#pragma unroll
        for (int i = 0; i < 16; i++) {
            float4 fa = erow[2 * i];
            float4 fb = erow[2 * i + 1];
            __nv_bfloat162 p0 = __floats2bfloat162_rn(fa.x, fa.y);
            __nv_bfloat162 p1 = __floats2bfloat162_rn(fa.z, fa.w);
            __nv_bfloat162 p2 = __floats2bfloat162_rn(fb.x, fb.y);
            __nv_bfloat162 p3 = __floats2bfloat162_rn(fb.z, fb.w);
            uint4 v;
            v.x = *(uint32_t*)&p0; v.y = *(uint32_t*)&p1;
            v.z = *(uint32_t*)&p2; v.w = *(uint32_t*)&p3;
            *(uint4*)(dst + i * 16) = v;
        }
    }
    __syncthreads();

    // Main MMA loop
    float acc[8][4];
#pragma unroll
    for (int nb = 0; nb < 8; nb++)
#pragma unroll
        for (int r = 0; r < 4; r++) acc[nb][r] = 0.f;

    const char* Ar0 = smem + SM_A + (16 * wid + g) * ASTRIDE + tg * 4;
    const char* Ar8 = Ar0 + 8 * ASTRIDE;
    const char* Bt0 = smem + SM_B + g * ASTRIDE + tg * 4;

#pragma unroll 4
    for (int ks = 0; ks < 16; ks++) {
        const int kb = ks * 32;   // 16 bf16 = 32 bytes
        uint32_t a0 = *(const uint32_t*)(Ar0 + kb);
        uint32_t a1 = *(const uint32_t*)(Ar8 + kb);
        uint32_t a2 = *(const uint32_t*)(Ar0 + kb + 16);
        uint32_t a3 = *(const uint32_t*)(Ar8 + kb + 16);
#pragma unroll
        for (int nb = 0; nb < 8; nb++) {
            uint32_t b0 = *(const uint32_t*)(Bt0 + nb * 8 * ASTRIDE + kb);
            uint32_t b1 = *(const uint32_t*)(Bt0 + nb * 8 * ASTRIDE + kb + 16);
            mma_bf16(acc[nb][0], acc[nb][1], acc[nb][2], acc[nb][3],
                     a0, a1, a2, a3, b0, b1);
        }
    }

    // Epilogue: +bias, exp, store
    {
        const float* bsh = (const float*)(smem + SM_BIAS);
        float* out0 = g_eexp + ((size_t)blockIdx.x * 128 + 16 * wid + g) * Tt;
        float* out8 = out0 + 8 * Tt;
#pragma unroll
        for (int nb = 0; nb < 8; nb++) {
            const int c0 = nb * 8 + tg * 2;
            float bA = bsh[c0], bB = bsh[c0 + 1];
            float2 v0, v1;
            v0.x = __expf(acc[nb][0] + bA);
            v0.y = __expf(acc[nb][1] + bB);
            v1.x = __expf(acc[nb][2] + bA);
            v1.y = __expf(acc[nb][3] + bB);
            *(float2*)(out0 + c0) = v0;
            *(float2*)(out8 + c0) = v1;
        }
    }
}

// =====================================================================
// Kernel 2: CRF forward (linear space, renorm by q[4] every 4 steps)
//   1 CTA/sequence, 64 threads; thread j owns state j.
// =====================================================================
__global__ void __launch_bounds__(64, 1)
crf_kernel(const int* __restrict__ tags, const float* __restrict__ trans)
{
    __shared__ __align__(16) float qs[2][Tt];
    __shared__ float sc[Tt];

    const int b = blockIdx.x;
    const int j = threadIdx.x;
    const uint32_t qb = smem_u32(&qs[0][0]);

    // exp(trans) column j, packed over i-pairs
    u64 E2[32];
#pragma unroll
    for (int i = 0; i < 32; i++) {
        float ea = __expf(trans[(2 * i) * Tt + j]);
        float eb = __expf(trans[(2 * i + 1) * Tt + j]);
        E2[i] = pack2(ea, eb);
    }
    const float Eend = __expf(trans[j * Tt + 1]);   // exp(trans[j, END])

    const float* ee = g_eexp + (size_t)b * Ln * Tt;
    const int*   tg = tags + b * Ln;

    // gold path score (partial per thread)
    float s = 0.f;
    for (int t = j; t < Ln; t += Tt) {
        int tt = tg[t];
        s += __logf(ee[t * Tt + tt]);
        s += (t == 0) ? trans[tt] : trans[tg[t - 1] * Tt + tt];
        if (t == Ln - 1) s += trans[tt * Tt + 1];
    }
    sc[j] = s;

    // init: q0 = exp(trans[START,j]) * eexp[0,j]
    float q = __expf(trans[j]) * ee[j];
    qs[0][j] = q;
    float C = 0.f;
    float eeA = ee[1 * Tt + j];
    float eeB = ee[2 * Tt + j];
    float eeC = ee[3 * Tt + j];
    __syncthreads();

    for (int t = 1; t < Ln; t++) {
        const int rb = (t - 1) & 1;
        const uint32_t qa = qb + rb * (Tt * 4);

        float em = eeA;
        eeA = eeB; eeB = eeC;
        if (t + 3 < Ln) eeC = ee[(t + 3) * Tt + j];

        float rinv = 1.0f;
        const bool rn = ((t & 3) == 0);
        if (rn) {
            float m = qs[rb][4];          // generic label state: always > 0
            C += __logf(m);
            rinv = __fdividef(1.0f, m);
        }

        u64 a0 = 0ull, a1 = 0ull, a2 = 0ull, a3 = 0ull;
#pragma unroll
        for (int i = 0; i < 32; i += 8) {
            u64 x0, x1, x2, x3, x4, x5, x6, x7;
            lds_v2u64(x0, x1, qa + (i + 0) * 8);
            lds_v2u64(x2, x3, qa + (i + 2) * 8);
            lds_v2u64(x4, x5, qa + (i + 4) * 8);
            lds_v2u64(x6, x7, qa + (i + 6) * 8);
            ffma2(a0, x0, E2[i + 0]); ffma2(a1, x1, E2[i + 1]);
            ffma2(a2, x2, E2[i + 2]); ffma2(a3, x3, E2[i + 3]);
            ffma2(a0, x4, E2[i + 4]); ffma2(a1, x5, E2[i + 5]);
            ffma2(a2, x6, E2[i + 6]); ffma2(a3, x7, E2[i + 7]);
        }
        float f0, f1, f2, f3, f4, f5, f6, f7;
        unpack2(a0, f0, f1); unpack2(a1, f2, f3);
        unpack2(a2, f4, f5); unpack2(a3, f6, f7);
        float dot = ((f0 + f1) + (f2 + f3)) + ((f4 + f5) + (f6 + f7));

        q = dot * em;
        if (rn) q *= rinv;
        qs[t & 1][j] = q;
        __syncthreads();
    }

    qs[0][j] = q * Eend;
    __syncthreads();
    if (j == 0) {
        float Z = 0.f, S = 0.f;
#pragma unroll
        for (int i = 0; i < Tt; i++) { Z += qs[0][i]; S += sc[i]; }
        g_nll[b] = (C + __logf(Z)) - S;
    }
}

// =====================================================================
// Kernel 3: deterministic reduce
// =====================================================================
__global__ void reduce_kernel(float* out)
{
    __shared__ float sh[Bn];
    int i = threadIdx.x;
    sh[i] = g_nll[i];
    __syncthreads();
    if (i == 0) {
        float s = 0.f;
#pragma unroll
        for (int k = 0; k < Bn; k++) s += sh[k];
        out[0] = s;
    }
}

// =====================================================================
// Launch: 0:x 1:tags 2:mask(unused) 3:embed 4:W 5:b 6:trans
// =====================================================================
extern "C" void kernel_launch(void* const* d_in, const int* in_sizes, int n_in,
                              void* d_out, int out_size)
{
    const int*   x     = (const int*)d_in[0];
    const int*   tags  = (const int*)d_in[1];
    const float* embed = (const float*)d_in[3];
    const float* W     = (const float*)d_in[4];
    const float* bias  = (const float*)d_in[5];
    const float* trans = (const float*)d_in[6];
    (void)in_sizes; (void)n_in; (void)out_size;

    cudaFuncSetAttribute(emit_mma,
                         cudaFuncAttributeMaxDynamicSharedMemorySize, EMIT_SMEM);

    wt_prep<<<1, 256>>>(W);
    emit_mma<<<(Bn * Ln) / 128, 256, EMIT_SMEM>>>(x, embed, bias);
    crf_kernel<<<Bn, Tt>>>(tags, trans);
    reduce_kernel<<<1, Bn>>>((float*)d_out);
}